// round 5
// baseline (speedup 1.0000x reference)
#include <cuda_runtime.h>

// B=16, N=32, C=8, O=16. Output (fp32) concat: out0@0(256), out1@256(8192),
// out2@8448(262144), out3@270592(8388608). Total 8659200.
constexpr int OFF1 = 256;
constexpr int OFF2 = 256 + 8192;
constexpr int OFF3 = 256 + 8192 + 262144;

#define DINL __device__ __forceinline__

// Scratch (device globals, allocation-free).
__device__ __align__(16) float g_r1[16 * 16];            // [b][max8|min8]
__device__ __align__(16) float g_r2[16 * 32 * 16];       // [b,i][max8|min8]
__device__ __align__(16) float g_r3[16 * 32 * 32 * 16];  // [b,i,j][max8|min8]
// Combined x2-permutation tables for out3 (b3 folded into V):
// V[b,u,v,o] = x2[b,u,v]*W3[0:8]  + x2[b,v,u]*W3[32:40] + b3  (used at (i, row))
// W[b,u,v,o] = x2[b,u,v]*W3[16:24] + x2[b,v,u]*W3[48:56]      (used at (i, col))
// U[b,u,v,o] = x2[b,u,v]*W3[64:72] + x2[b,v,u]*W3[80:88]      (used at (row, col))
__device__ __align__(16) float g_V[16 * 32 * 32 * 16];
__device__ __align__(16) float g_W[16 * 32 * 32 * 16];
__device__ __align__(16) float g_U[16 * 32 * 32 * 16];

DINL unsigned long long pk2(float lo, float hi) {
    unsigned long long r;
    asm("mov.b64 %0, {%1,%2};" : "=l"(r) : "f"(lo), "f"(hi));
    return r;
}
DINL void upk2(unsigned long long v, float& lo, float& hi) {
    asm("mov.b64 {%0,%1}, %2;" : "=f"(lo), "=f"(hi) : "l"(v));
}
DINL void fma2(unsigned long long& d, unsigned long long a, unsigned long long b) {
    asm("fma.rn.f32x2 %0, %1, %2, %0;" : "+l"(d) : "l"(a), "l"(b));
}
DINL float sigmoidf(float x) { return 1.f / (1.f + __expf(-x)); }

// ----------------------------------------------------------------------------
// Kernel 1a: reductions r3/r2/r1. Thread per (row, channel-pair).
// ----------------------------------------------------------------------------
extern "C" __global__ void __launch_bounds__(256) k_reduce(
    const float* __restrict__ x1, const float* __restrict__ x2,
    const float* __restrict__ x3)
{
    const int bx = blockIdx.x, tid = threadIdx.x;

    if (bx < 256) {
        const int gid = bx * 256 + tid;
        const int row = gid >> 2, cp = gid & 3;   // row = b*1024 + i*32 + j
        const int j = row & 31;
        const float2* p = (const float2*)(x3 + row * 256) + cp;
        float mx0 = -1e30f, mx1 = -1e30f, mn0 = 1e30f, mn1 = 1e30f;
        #pragma unroll
        for (int k = 0; k < 32; k++) {
            const float2 v = p[k * 4];
            const bool ex = (k == j);
            mx0 = fmaxf(mx0, ex ? 0.f : v.x);
            mx1 = fmaxf(mx1, ex ? 0.f : v.y);
            mn0 = fminf(mn0, ex ? 1.f : v.x);
            mn1 = fminf(mn1, ex ? 1.f : v.y);
        }
        float* d = g_r3 + row * 16 + cp * 2;
        d[0] = mx0; d[1] = mx1; d[8] = mn0; d[9] = mn1;
    } else if (bx < 264) {
        const int gid = (bx - 256) * 256 + tid;
        const int row = gid >> 2, cp = gid & 3;   // row = b*32 + i
        const int i = row & 31;
        const float2* p = (const float2*)(x2 + row * 256) + cp;
        float mx0 = -1e30f, mx1 = -1e30f, mn0 = 1e30f, mn1 = 1e30f;
        #pragma unroll
        for (int jn = 0; jn < 32; jn++) {
            const float2 v = p[jn * 4];
            const bool ex = (jn == i);
            mx0 = fmaxf(mx0, ex ? 0.f : v.x);
            mx1 = fmaxf(mx1, ex ? 0.f : v.y);
            mn0 = fminf(mn0, ex ? 1.f : v.x);
            mn1 = fminf(mn1, ex ? 1.f : v.y);
        }
        float* d = g_r2 + row * 16 + cp * 2;
        d[0] = mx0; d[1] = mx1; d[8] = mn0; d[9] = mn1;
    } else {
        if (tid < 64) {
            const int row = tid >> 2, cp = tid & 3;   // row = b
            const float2* p = (const float2*)(x1 + row * 256) + cp;
            float mx0 = -1e30f, mx1 = -1e30f, mn0 = 1e30f, mn1 = 1e30f;
            #pragma unroll
            for (int nn = 0; nn < 32; nn++) {
                const float2 v = p[nn * 4];
                mx0 = fmaxf(mx0, v.x);
                mx1 = fmaxf(mx1, v.y);
                mn0 = fminf(mn0, v.x);
                mn1 = fminf(mn1, v.y);
            }
            float* d = g_r1 + row * 16 + cp * 2;
            d[0] = mx0; d[1] = mx1; d[8] = mn0; d[9] = mn1;
        }
    }
}

// ----------------------------------------------------------------------------
// Kernel 1b: x2 tables V/W/U. Thread per (b,u,v,o): 262144 threads.
// ----------------------------------------------------------------------------
extern "C" __global__ void __launch_bounds__(256) k_tables(
    const float* __restrict__ x2, const float* __restrict__ W3,
    const float* __restrict__ b3)
{
    __shared__ float sW[96 * 16];
    __shared__ float sb[16];
    const int bx = blockIdx.x, tid = threadIdx.x;
    for (int idx = tid; idx < 1536; idx += 256) sW[idx] = W3[idx];
    if (tid < 16) sb[tid] = b3[tid];
    __syncthreads();

    const int gid = bx * 256 + tid;
    const int o = gid & 15;
    const int e = gid >> 4;            // b*1024 + u*32 + v
    const int b = e >> 10;
    const int u = (e >> 5) & 31, v = e & 31;

    const float4* pa = (const float4*)(x2 + e * 8);
    const float4* pb = (const float4*)(x2 + (b * 1024 + v * 32 + u) * 8);
    const float4 a0 = pa[0], a1 = pa[1];
    const float4 b0v = pb[0], b1v = pb[1];
    float xa[8] = {a0.x, a0.y, a0.z, a0.w, a1.x, a1.y, a1.z, a1.w};
    float xb[8] = {b0v.x, b0v.y, b0v.z, b0v.w, b1v.x, b1v.y, b1v.z, b1v.w};

    float sv = sb[o], sw = 0.f, su = 0.f;
    #pragma unroll
    for (int cc = 0; cc < 8; cc++) {
        sv += xa[cc] * sW[cc * 16 + o]        + xb[cc] * sW[(32 + cc) * 16 + o];
        sw += xa[cc] * sW[(16 + cc) * 16 + o] + xb[cc] * sW[(48 + cc) * 16 + o];
        su += xa[cc] * sW[(64 + cc) * 16 + o] + xb[cc] * sW[(80 + cc) * 16 + o];
    }
    g_V[gid] = sv;
    g_W[gid] = sw;
    g_U[gid] = su;
}

// ----------------------------------------------------------------------------
// Kernel 2: out0/out1/out2. Warp per row; lanes = (o 0..15) x (half 0..1).
// ----------------------------------------------------------------------------
extern "C" __global__ void __launch_bounds__(256) k_out_small(
    const float* __restrict__ x0, const float* __restrict__ x1,
    const float* __restrict__ x2,
    const float* __restrict__ W0, const float* __restrict__ b0,
    const float* __restrict__ W1, const float* __restrict__ b1,
    const float* __restrict__ W2, const float* __restrict__ b2,
    float* __restrict__ out)
{
    __shared__ float sW2[64 * 16];
    __shared__ float sb2[16];
    const int bx = blockIdx.x, tid = threadIdx.x;
    const int warp = tid >> 5, lane = tid & 31;
    const int o = lane & 15, hf = lane >> 4;

    for (int idx = tid; idx < 1024; idx += 256) sW2[idx] = W2[idx];
    if (tid < 16) sb2[tid] = b2[tid];
    __syncthreads();

    if (bx < 2048) {  // out2
        const int row = bx * 8 + warp;  // (b,i,j)
        const int b = row >> 10, i = (row >> 5) & 31, j = row & 31;
        const int u = hf ? j : i, v = hf ? i : j;
        const int wb = hf * 32;
        const float* px1 = x1 + (b * 32 + u) * 8;
        const float* px2 = x2 + ((b * 32 + u) * 32 + v) * 8;
        const float* pr3 = g_r3 + ((b * 32 + u) * 32 + v) * 16;
        float acc = 0.f;
        #pragma unroll
        for (int cc = 0; cc < 8; cc++)  acc += px1[cc] * sW2[(wb + cc) * 16 + o];
        #pragma unroll
        for (int cc = 0; cc < 8; cc++)  acc += px2[cc] * sW2[(wb + 8 + cc) * 16 + o];
        #pragma unroll
        for (int cc = 0; cc < 16; cc++) acc += pr3[cc] * sW2[(wb + 16 + cc) * 16 + o];
        acc += __shfl_xor_sync(~0u, acc, 16);
        if (hf == 0) out[OFF2 + row * 16 + o] = sigmoidf(acc + sb2[o]);
    } else if (bx < 2112) {  // out1
        const int row = (bx - 2048) * 8 + warp;  // (b,i)
        const int b = row >> 5;
        float acc = 0.f;
        if (hf == 0) {
            const float* px0 = x0 + b * 8;
            const float* px1 = x1 + row * 8;
            #pragma unroll
            for (int cc = 0; cc < 8; cc++) acc += px0[cc] * __ldg(W1 + cc * 16 + o);
            #pragma unroll
            for (int cc = 0; cc < 8; cc++) acc += px1[cc] * __ldg(W1 + (8 + cc) * 16 + o);
        } else {
            const float* pr2 = g_r2 + row * 16;
            #pragma unroll
            for (int cc = 0; cc < 16; cc++) acc += pr2[cc] * __ldg(W1 + (16 + cc) * 16 + o);
        }
        acc += __shfl_xor_sync(~0u, acc, 16);
        if (hf == 0) out[OFF1 + row * 16 + o] = sigmoidf(acc + __ldg(b1 + o));
    } else {  // out0
        for (int bb = warp; bb < 16; bb += 8) {
            float acc = 0.f;
            if (hf == 0) {
                #pragma unroll
                for (int c2 = 0; c2 < 12; c2++) {
                    const float f = (c2 < 8) ? x0[bb * 8 + c2] : g_r1[bb * 16 + c2 - 8];
                    acc += f * __ldg(W0 + c2 * 16 + o);
                }
            } else {
                #pragma unroll
                for (int c2 = 12; c2 < 24; c2++)
                    acc += g_r1[bb * 16 + c2 - 8] * __ldg(W0 + c2 * 16 + o);
            }
            acc += __shfl_xor_sync(~0u, acc, 16);
            if (hf == 0) out[bb * 16 + o] = sigmoidf(acc + __ldg(b0 + o));
        }
    }
}

// ----------------------------------------------------------------------------
// Kernel 3: out3. Block per (b,i). Symmetric-pair scheme: the 6 data vectors
// of element (j,k) are the same 6 vectors as element (k,j), so each iteration
// computes BOTH results (4 accumulator chains, 2 outputs each) from 12 LDS.128
// -> half the shared loads per result and 4 independent FFMA2 chains.
// Thread = (k = tid>>3, og = tid&7); pairs via j = (k+d)&31, d=1..16.
// ----------------------------------------------------------------------------
extern "C" __global__ void __launch_bounds__(256, 1) k_out3(
    const float* __restrict__ x3, const float* __restrict__ W3,
    float* __restrict__ out)
{
    extern __shared__ float sm[];
    float* sA  = sm;            // x3[b,i,u,v,:]  [u*264 + v*8]
    float* sB  = sm + 8448;     // x3[b,u,i,v,:]
    float* sC  = sm + 16896;    // x3[b,u,v,i,:]
    float* sV  = sm + 25344;    // g_V[b,i,:,:]   512 floats
    float* sWt = sm + 25856;    // g_W[b,i,:,:]   512 floats

    const int bx = blockIdx.x, tid = threadIdx.x;
    const int b = bx >> 5, i = bx & 31;

    {
        const int base_bi = bx * 8192;
        const int base_b = b * 262144;
        for (int idx = tid; idx < 8192; idx += 256) {
            const int u = idx >> 8;
            const int r = idx & 255;           // v*8 + c
            const int v = r >> 3, c = r & 7;
            const int dst = u * 264 + r;
            sA[dst] = x3[base_bi + idx];
            sB[dst] = x3[base_b + u * 8192 + i * 256 + r];
            sC[dst] = x3[base_b + u * 8192 + v * 256 + i * 8 + c];
        }
        for (int idx = tid; idx < 512; idx += 256) {
            sV[idx]  = g_V[bx * 512 + idx];
            sWt[idx] = g_W[bx * 512 + idx];
        }
    }

    const int og = tid & 7;
    const int k = tid >> 3;

    // Weight channel-pairs in regs: wA for output 2og, wB for 2og+1.
    // wX[t*4+p] = {W3[16t+8+2p, o], W3[16t+8+2p+1, o]}
    unsigned long long wA[24], wB[24];
    #pragma unroll
    for (int t = 0; t < 6; t++) {
        #pragma unroll
        for (int p = 0; p < 4; p++) {
            const int r0 = (16 * t + 8 + 2 * p) * 16;
            const int r1 = r0 + 16;
            wA[t * 4 + p] = pk2(__ldg(W3 + r0 + 2 * og),     __ldg(W3 + r1 + 2 * og));
            wB[t * 4 + p] = pk2(__ldg(W3 + r0 + 2 * og + 1), __ldg(W3 + r1 + 2 * og + 1));
        }
    }
    __syncthreads();

    const int ko = k * 264, k8 = k * 8;
    const int outb = OFF3 + bx * 16384 + 2 * og;          // + row*512 + col*16
    const float* pU = g_U + b * 16384 + 2 * og;           // + row*512 + col*16
    const float2 Vk = *(const float2*)(sV + k * 16 + 2 * og);
    const float2 Wk = *(const float2*)(sWt + k * 16 + 2 * og);

#define DOT4(acc, q0, q1, w, T)                                        \
    fma2(acc, q0.x, w[(T) * 4 + 0]); fma2(acc, q0.y, w[(T) * 4 + 1]);  \
    fma2(acc, q1.x, w[(T) * 4 + 2]); fma2(acc, q1.y, w[(T) * 4 + 3]);

    // ----- diagonal (j == k) -----
    {
        const float2 Ud = *(const float2*)(pU + k * 528);
        const ulonglong2* qa = (const ulonglong2*)(sA + ko + k8);
        const ulonglong2* qb = (const ulonglong2*)(sB + ko + k8);
        const ulonglong2* qc = (const ulonglong2*)(sC + ko + k8);
        const ulonglong2 a0 = qa[0], a1 = qa[1];
        const ulonglong2 b0 = qb[0], b1 = qb[1];
        const ulonglong2 c0 = qc[0], c1 = qc[1];
        unsigned long long accA = 0ull, accB = 0ull;
        DOT4(accA, a0, a1, wA, 0); DOT4(accB, a0, a1, wB, 0);
        DOT4(accA, a0, a1, wA, 1); DOT4(accB, a0, a1, wB, 1);
        DOT4(accA, b0, b1, wA, 2); DOT4(accB, b0, b1, wB, 2);
        DOT4(accA, b0, b1, wA, 3); DOT4(accB, b0, b1, wB, 3);
        DOT4(accA, c0, c1, wA, 4); DOT4(accB, c0, c1, wB, 4);
        DOT4(accA, c0, c1, wA, 5); DOT4(accB, c0, c1, wB, 5);
        float a0f, a1f, b0f, b1f;
        upk2(accA, a0f, a1f);
        upk2(accB, b0f, b1f);
        float2 rr;
        rr.x = sigmoidf(a0f + a1f + Vk.x + Wk.x + Ud.x);
        rr.y = sigmoidf(b0f + b1f + Vk.y + Wk.y + Ud.y);
        *(float2*)(out + outb + k * 528) = rr;
    }

    // ----- off-diagonal pairs -----
    #pragma unroll 1
    for (int d = 1; d <= 16; d++) {
        if (d == 16 && k >= 16) break;
        const int j = (k + d) & 31;
        const int jo = j * 264, j8 = j * 8;

        // U for both orders (issue early; ~200cyc L2 latency hidden by fma block)
        const float2 Ujk = *(const float2*)(pU + j * 512 + k * 16);
        const float2 Ukj = *(const float2*)(pU + k * 512 + j * 16);

        const ulonglong2* q;
        q = (const ulonglong2*)(sA + jo + k8); const ulonglong2 Ajk0 = q[0], Ajk1 = q[1];
        q = (const ulonglong2*)(sA + ko + j8); const ulonglong2 Akj0 = q[0], Akj1 = q[1];
        q = (const ulonglong2*)(sB + jo + k8); const ulonglong2 Bjk0 = q[0], Bjk1 = q[1];
        q = (const ulonglong2*)(sB + ko + j8); const ulonglong2 Bkj0 = q[0], Bkj1 = q[1];
        q = (const ulonglong2*)(sC + jo + k8); const ulonglong2 Cjk0 = q[0], Cjk1 = q[1];
        q = (const ulonglong2*)(sC + ko + j8); const ulonglong2 Ckj0 = q[0], Ckj1 = q[1];

        unsigned long long aJA = 0ull, aJB = 0ull, aKA = 0ull, aKB = 0ull;
        // result (row=j, col=k): terms T0..T5 with (Ajk,Akj,Bjk,Bkj,Cjk,Ckj)
        // result (row=k, col=j): same vectors, term indices swapped in pairs
        DOT4(aJA, Ajk0, Ajk1, wA, 0); DOT4(aJB, Ajk0, Ajk1, wB, 0);
        DOT4(aKA, Ajk0, Ajk1, wA, 1); DOT4(aKB, Ajk0, Ajk1, wB, 1);
        DOT4(aJA, Akj0, Akj1, wA, 1); DOT4(aJB, Akj0, Akj1, wB, 1);
        DOT4(aKA, Akj0, Akj1, wA, 0); DOT4(aKB, Akj0, Akj1, wB, 0);
        DOT4(aJA, Bjk0, Bjk1, wA, 2); DOT4(aJB, Bjk0, Bjk1, wB, 2);
        DOT4(aKA, Bjk0, Bjk1, wA, 3); DOT4(aKB, Bjk0, Bjk1, wB, 3);
        DOT4(aJA, Bkj0, Bkj1, wA, 3); DOT4(aJB, Bkj0, Bkj1, wB, 3);
        DOT4(aKA, Bkj0, Bkj1, wA, 2); DOT4(aKB, Bkj0, Bkj1, wB, 2);
        DOT4(aJA, Cjk0, Cjk1, wA, 4); DOT4(aJB, Cjk0, Cjk1, wB, 4);
        DOT4(aKA, Cjk0, Cjk1, wA, 5); DOT4(aKB, Cjk0, Cjk1, wB, 5);
        DOT4(aJA, Ckj0, Ckj1, wA, 5); DOT4(aJB, Ckj0, Ckj1, wB, 5);
        DOT4(aKA, Ckj0, Ckj1, wA, 4); DOT4(aKB, Ckj0, Ckj1, wB, 4);

        const float2 Vj = *(const float2*)(sV + j * 16 + 2 * og);
        const float2 Wj = *(const float2*)(sWt + j * 16 + 2 * og);

        float x0f, x1f, y0f, y1f;
        upk2(aJA, x0f, x1f);
        upk2(aJB, y0f, y1f);
        float2 rJ;
        rJ.x = sigmoidf(x0f + x1f + Vj.x + Wk.x + Ujk.x);
        rJ.y = sigmoidf(y0f + y1f + Vj.y + Wk.y + Ujk.y);
        *(float2*)(out + outb + j * 512 + k * 16) = rJ;

        upk2(aKA, x0f, x1f);
        upk2(aKB, y0f, y1f);
        float2 rK;
        rK.x = sigmoidf(x0f + x1f + Vk.x + Wj.x + Ukj.x);
        rK.y = sigmoidf(y0f + y1f + Vk.y + Wj.y + Ukj.y);
        *(float2*)(out + outb + k * 512 + j * 16) = rK;
    }
#undef DOT4
}

// ----------------------------------------------------------------------------
extern "C" void kernel_launch(void* const* d_in, const int* in_sizes, int n_in,
                              void* d_out, int out_size) {
    const float *x0 = nullptr, *x1 = nullptr, *x2 = nullptr, *x3 = nullptr;
    const float *W0 = nullptr, *W1 = nullptr, *W2 = nullptr, *W3 = nullptr;
    const float* bs[4] = {nullptr, nullptr, nullptr, nullptr};
    int nb = 0;
    for (int ii = 0; ii < n_in; ii++) {
        const float* p = (const float*)d_in[ii];
        switch (in_sizes[ii]) {
            case 128:     x0 = p; break;
            case 4096:    x1 = p; break;
            case 131072:  x2 = p; break;
            case 4194304: x3 = p; break;
            case 384:     W0 = p; break;
            case 512:     W1 = p; break;
            case 1024:    W2 = p; break;
            case 1536:    W3 = p; break;
            case 16:      if (nb < 4) bs[nb++] = p; break;
        }
    }
    const float *b0 = bs[0], *b1 = bs[1], *b2 = bs[2], *b3 = bs[3];
    float* out = (float*)d_out;

    cudaFuncSetAttribute(k_out3, cudaFuncAttributeMaxDynamicSharedMemorySize, 105472);

    k_reduce<<<265, 256>>>(x1, x2, x3);
    k_tables<<<1024, 256>>>(x2, W3, b3);
    k_out_small<<<2113, 256>>>(x0, x1, x2, W0, b0, W1, b1, W2, b2, out);
    k_out3<<<512, 256, 105472>>>(x3, W3, out);
}